// round 4
// baseline (speedup 1.0000x reference)
#include <cuda_runtime.h>

#define NODES 100000
#define EDGES 640000
#define DIM   128
#define NDIN  239
#define NEG   0.01f

// ---- scratch (no allocs allowed; __device__ globals) ----
__device__ float g_bufA[(size_t)NODES * DIM];
__device__ float g_bufB[(size_t)NODES * DIM];
__device__ float g_bufC[(size_t)NODES * DIM];
__device__ float g_deg[NODES];
__device__ float g_dinv[NODES];
__device__ float g_norm[EDGES];

// ---------------- graph-structure kernels ----------------
__global__ void k_zero_deg() {
    int i = blockIdx.x * blockDim.x + threadIdx.x;
    if (i < NODES) g_deg[i] = 0.f;
}

__global__ void k_deg(const int* __restrict__ ei) {
    int e = blockIdx.x * blockDim.x + threadIdx.x;
    if (e < EDGES) {
        int d = ei[EDGES + e];
        if (d >= 0 && d < NODES) atomicAdd(&g_deg[d], 1.f);
    }
}

__global__ void k_dinv() {
    int i = blockIdx.x * blockDim.x + threadIdx.x;
    if (i < NODES) g_dinv[i] = rsqrtf(g_deg[i] + 1.f);
}

__global__ void k_norm(const int* __restrict__ ei) {
    int e = blockIdx.x * blockDim.x + threadIdx.x;
    if (e < EDGES) {
        int s = ei[e];
        int d = ei[EDGES + e];
        g_norm[e] = g_dinv[s] * g_dinv[d];
    }
}

// ---------------- GEMM: out[M,128] = A[M,K] @ W[K,128] ----------------
// Block: 64 rows x 128 cols, blockDim (32,8). Each thread: 8 rows x 4 cols.
// LEAKY: out = leaky(acc + bias)
// CONV : out = acc (pre-agg "hw"); agg = acc*dinv[row]^2 + bias   (GCN self-loop fused)
template <bool LEAKY, bool CONV>
__global__ void k_gemm(const float* __restrict__ A, const float* __restrict__ W,
                       const float* __restrict__ bias,
                       float* __restrict__ out, float* __restrict__ agg,
                       int M, int K) {
    __shared__ float xs[64 * 16];
    __shared__ float ws[16 * 128];

    int tx = threadIdx.x;          // 0..31  (cols: 4*tx .. 4*tx+3)
    int ty = threadIdx.y;          // 0..7   (rows: ty + 8*i)
    int tid = ty * 32 + tx;
    int row0 = blockIdx.x * 64;

    float4 acc[8];
#pragma unroll
    for (int i = 0; i < 8; i++) acc[i] = make_float4(0.f, 0.f, 0.f, 0.f);

    int nch = (K + 15) >> 4;
    for (int ch = 0; ch < nch; ch++) {
        int k0 = ch << 4;
        // load A tile [64][16]
#pragma unroll
        for (int j = 0; j < 4; j++) {
            int idx = tid + 256 * j;
            int r = idx >> 4, c = idx & 15;
            int gr = row0 + r, gc = k0 + c;
            xs[idx] = (gr < M && gc < K) ? A[(long)gr * K + gc] : 0.f;
        }
        // load W tile [16][128] as float4
#pragma unroll
        for (int j = 0; j < 2; j++) {
            int idx = tid + 256 * j;        // float4 index 0..511
            int k = idx >> 5, c4 = idx & 31;
            float4 v = make_float4(0.f, 0.f, 0.f, 0.f);
            if (k0 + k < K) v = *(const float4*)&W[(long)(k0 + k) * 128 + c4 * 4];
            *(float4*)&ws[k * 128 + c4 * 4] = v;
        }
        __syncthreads();
#pragma unroll
        for (int k = 0; k < 16; k++) {
            float4 w = *(float4*)&ws[k * 128 + tx * 4];
#pragma unroll
            for (int i = 0; i < 8; i++) {
                float a = xs[(ty + 8 * i) * 16 + k];
                acc[i].x = fmaf(a, w.x, acc[i].x);
                acc[i].y = fmaf(a, w.y, acc[i].y);
                acc[i].z = fmaf(a, w.z, acc[i].z);
                acc[i].w = fmaf(a, w.w, acc[i].w);
            }
        }
        __syncthreads();
    }

    float4 b4 = *(const float4*)&bias[tx * 4];
#pragma unroll
    for (int i = 0; i < 8; i++) {
        int r = row0 + ty + 8 * i;
        if (r >= M) continue;
        float4 v = acc[i];
        if (CONV) {
            *(float4*)&out[(long)r * 128 + tx * 4] = v;   // hw (for edge scatter)
            float di = g_dinv[r];
            float s = di * di;
            float4 a2 = make_float4(fmaf(v.x, s, b4.x), fmaf(v.y, s, b4.y),
                                    fmaf(v.z, s, b4.z), fmaf(v.w, s, b4.w));
            *(float4*)&agg[(long)r * 128 + tx * 4] = a2;
        } else {
            v.x += b4.x; v.y += b4.y; v.z += b4.z; v.w += b4.w;
            if (LEAKY) {
                v.x = fmaxf(v.x, NEG * v.x);
                v.y = fmaxf(v.y, NEG * v.y);
                v.z = fmaxf(v.z, NEG * v.z);
                v.w = fmaxf(v.w, NEG * v.w);
            }
            *(float4*)&out[(long)r * 128 + tx * 4] = v;
        }
    }
}

// ---------------- edge scatter: agg[dst] += hw[src] * norm ----------------
// One warp per edge; each lane handles one float4 (32*4 = 128 dims).
// Uses sm_90+ vector reduction red.global.add.v4.f32 (1 RED per 16B).
__global__ void k_scatter(const int* __restrict__ ei,
                          const float* __restrict__ hw,
                          float* __restrict__ agg) {
    int idx = blockIdx.x * blockDim.x + threadIdx.x;
    int e = idx >> 5;
    int c = idx & 31;
    if (e >= EDGES) return;
    int src = ei[e];
    int dst = ei[EDGES + e];
    float n = g_norm[e];
    float4 v = *(const float4*)&hw[(long)src * 128 + c * 4];
    float* p = &agg[(long)dst * 128 + c * 4];
    asm volatile("red.global.add.v4.f32 [%0], {%1, %2, %3, %4};"
                 :: "l"(p), "f"(v.x * n), "f"(v.y * n), "f"(v.z * n), "f"(v.w * n)
                 : "memory");
}

// ---------------- final projection: out[M,2] = h[M,128] @ W[128,2] + b ----------------
// One warp per row; lane loads one float4 of the row.
__global__ void k_out(const float* __restrict__ h, const float* __restrict__ W,
                      const float* __restrict__ b, float* __restrict__ out) {
    __shared__ float ws[256];
    int tid = threadIdx.x;
    if (tid < 256) ws[tid] = W[tid];
    __syncthreads();
    int warp = (blockIdx.x * blockDim.x + tid) >> 5;
    int lane = tid & 31;
    if (warp >= NODES) return;
    float4 v = *(const float4*)&h[(long)warp * 128 + lane * 4];
    int k = lane * 4;
    float s0 = v.x * ws[(k + 0) * 2] + v.y * ws[(k + 1) * 2] +
               v.z * ws[(k + 2) * 2] + v.w * ws[(k + 3) * 2];
    float s1 = v.x * ws[(k + 0) * 2 + 1] + v.y * ws[(k + 1) * 2 + 1] +
               v.z * ws[(k + 2) * 2 + 1] + v.w * ws[(k + 3) * 2 + 1];
#pragma unroll
    for (int o = 16; o; o >>= 1) {
        s0 += __shfl_xor_sync(0xFFFFFFFFu, s0, o);
        s1 += __shfl_xor_sync(0xFFFFFFFFu, s1, o);
    }
    if (lane == 0) {
        out[(long)warp * 2 + 0] = s0 + b[0];
        out[(long)warp * 2 + 1] = s1 + b[1];
    }
}

// ---------------- launch ----------------
extern "C" void kernel_launch(void* const* d_in, const int* in_sizes, int n_in,
                              void* d_out, int out_size) {
    // Input-order detection (dict order expected; alphabetical hedge kept).
    int ix, iei, iwin, ibin, iwg, ibg, iwo1, ibo1, iwo2, ibo2;
    if (in_sizes[0] == 16384) {          // alphabetical
        iwg = 0; iwin = 1; iwo1 = 2; iwo2 = 3;
        ibg = 4; ibin = 5; ibo1 = 6; ibo2 = 7;
        iei = 8; /*edge_type=9*/ ix = 10;
    } else {                              // dict / insertion order (default)
        ix = 0; iei = 1; /*edge_type=2*/
        iwin = 3; ibin = 4; iwg = 5; ibg = 6;
        iwo1 = 7; ibo1 = 8; iwo2 = 9; ibo2 = 10;
    }

    const float* x    = (const float*)d_in[ix];
    const int*   ei   = (const int*)d_in[iei];   // int32! (JAX x64 disabled)
    const float* W_in = (const float*)d_in[iwin];
    const float* b_in = (const float*)d_in[ibin];
    const float* W_g  = (const float*)d_in[iwg];
    const float* b_g  = (const float*)d_in[ibg];
    const float* W_o1 = (const float*)d_in[iwo1];
    const float* b_o1 = (const float*)d_in[ibo1];
    const float* W_o2 = (const float*)d_in[iwo2];
    const float* b_o2 = (const float*)d_in[ibo2];
    float* out = (float*)d_out;

    float *bufA, *bufB, *bufC;
    cudaGetSymbolAddress((void**)&bufA, g_bufA);
    cudaGetSymbolAddress((void**)&bufB, g_bufB);
    cudaGetSymbolAddress((void**)&bufC, g_bufC);

    dim3 gblk(32, 8);
    int gemm_grid = (NODES + 63) / 64;
    int scat_grid = (EDGES * 32 + 255) / 256;

    // graph structure
    k_zero_deg<<<(NODES + 255) / 256, 256>>>();
    k_deg<<<(EDGES + 255) / 256, 256>>>(ei);
    k_dinv<<<(NODES + 255) / 256, 256>>>();
    k_norm<<<(EDGES + 255) / 256, 256>>>(ei);

    // h0 = leaky(x @ W_in + b_in)               -> bufA
    k_gemm<true, false><<<gemm_grid, gblk>>>(x, W_in, b_in, bufA, nullptr, NODES, NDIN);

    // conv1: hw = bufA @ W_g -> bufB ; agg = hw*dinv^2 + b_g -> bufC ; scatter
    k_gemm<false, true><<<gemm_grid, gblk>>>(bufA, W_g, b_g, bufB, bufC, NODES, DIM);
    k_scatter<<<scat_grid, 256>>>(ei, bufB, bufC);

    // conv2: hw = bufC @ W_g -> bufB ; agg -> bufA ; scatter
    k_gemm<false, true><<<gemm_grid, gblk>>>(bufC, W_g, b_g, bufB, bufA, NODES, DIM);
    k_scatter<<<scat_grid, 256>>>(ei, bufB, bufA);

    // h3 = leaky(bufA @ W_o1 + b_o1)            -> bufC
    k_gemm<true, false><<<gemm_grid, gblk>>>(bufA, W_o1, b_o1, bufC, nullptr, NODES, DIM);

    // out = bufC @ W_o2 + b_o2
    k_out<<<(NODES * 32 + 255) / 256, 256>>>(bufC, W_o2, b_o2, out);
}